// round 1
// baseline (speedup 1.0000x reference)
#include <cuda_runtime.h>
#include <cuda_bf16.h>
#include <math.h>

// Problem constants
#define BB 8
#define TT 2048
#define DD 1024
#define FF 4096
#define EE 8
#define KK 2

// GEMM tiling
#define BM 128
#define BN 128
#define BKK 16
#define TM 8
#define TN 8
#define NTHREADS 256

// Scratch (device globals: no allocation allowed)
__device__ float g_pooled[BB * DD];
__device__ int   g_eidx[BB * KK];
__device__ float g_ew[BB * KK];
__device__ float g_h[(size_t)BB * KK * TT * FF];   // 512 MB: gelu(x@W1+b1) per slot

// ---------------------------------------------------------------------------
// Kernel 1: mean-pool over T.  grid (B, D/256), block 256.
// ---------------------------------------------------------------------------
__global__ void pool_kernel(const float* __restrict__ x) {
    int b = blockIdx.x;
    int d = blockIdx.y * blockDim.x + threadIdx.x;
    const float* xp = x + (size_t)b * TT * DD + d;
    float s = 0.0f;
#pragma unroll 8
    for (int t = 0; t < TT; t++) s += xp[(size_t)t * DD];
    g_pooled[b * DD + d] = s * (1.0f / (float)TT);
}

// ---------------------------------------------------------------------------
// Kernel 2: logits = pooled @ Wr (8x8), top-2, softmax. One block, 8 warps.
// Warp w handles batch w.
// ---------------------------------------------------------------------------
__global__ void route_kernel(const float* __restrict__ Wr) {
    int w = threadIdx.x >> 5;
    int lane = threadIdx.x & 31;
    if (w >= BB) return;

    float sums[EE];
#pragma unroll
    for (int e = 0; e < EE; e++) sums[e] = 0.0f;

    for (int d = lane; d < DD; d += 32) {
        float p = g_pooled[w * DD + d];
        const float* wr = Wr + d * EE;
#pragma unroll
        for (int e = 0; e < EE; e++) sums[e] += p * wr[e];
    }
#pragma unroll
    for (int e = 0; e < EE; e++) {
#pragma unroll
        for (int off = 16; off > 0; off >>= 1)
            sums[e] += __shfl_xor_sync(0xFFFFFFFFu, sums[e], off);
    }

    if (lane == 0) {
        // top-1 (first index on tie, matches jax top_k)
        int i0 = 0; float v0 = sums[0];
#pragma unroll
        for (int e = 1; e < EE; e++) { if (sums[e] > v0) { v0 = sums[e]; i0 = e; } }
        // top-2
        int i1 = -1; float v1 = -1e30f;
#pragma unroll
        for (int e = 0; e < EE; e++) {
            if (e == i0) continue;
            if (sums[e] > v1) { v1 = sums[e]; i1 = e; }
        }
        // softmax over [v0, v1], v0 >= v1
        float e1 = expf(v1 - v0);
        float inv = 1.0f / (1.0f + e1);
        g_eidx[2 * w + 0] = i0;
        g_eidx[2 * w + 1] = i1;
        g_ew[2 * w + 0] = inv;
        g_ew[2 * w + 1] = e1 * inv;
    }
}

// ---------------------------------------------------------------------------
// Kernel 3: per slot s in [0,16): h[s] = gelu(x[b] @ W1[e] + b1[e])
// grid (FF/BN=32, TT/BM=16, 16), block 256, 128x128x16 tile, 8x8 microtile.
// ---------------------------------------------------------------------------
__global__ __launch_bounds__(NTHREADS, 2)
void gemm1_kernel(const float* __restrict__ x, const float* __restrict__ W1,
                  const float* __restrict__ b1) {
    __shared__ float As[BKK][BM + 4];
    __shared__ float Bs[BKK][BN + 4];

    int slot = blockIdx.z;
    int b = slot >> 1;
    int e = g_eidx[slot];
    const float* A  = x  + (size_t)b * TT * DD;     // (2048,1024)
    const float* Bm = W1 + (size_t)e * DD * FF;     // (1024,4096)
    float* C = g_h + (size_t)slot * TT * FF;        // (2048,4096)

    int tile_m = blockIdx.y * BM;
    int tile_n = blockIdx.x * BN;
    int tid = threadIdx.x;
    int tm = (tid >> 4) * TM;   // 0..120
    int tn = (tid & 15) * TN;   // 0..120

    float acc[TM][TN];
#pragma unroll
    for (int i = 0; i < TM; i++)
#pragma unroll
        for (int j = 0; j < TN; j++) acc[i][j] = 0.0f;

    for (int k0 = 0; k0 < DD; k0 += BKK) {
#pragma unroll
        for (int i = 0; i < 2; i++) {
            int l = tid + i * NTHREADS;          // 0..511
            int r  = l >> 2, c  = (l & 3) * 4;   // A: 128 rows x 16 cols
            float4 va = *(const float4*)(A + (size_t)(tile_m + r) * DD + k0 + c);
            As[c + 0][r] = va.x; As[c + 1][r] = va.y;
            As[c + 2][r] = va.z; As[c + 3][r] = va.w;
            int rb = l >> 5, cb = (l & 31) * 4;  // B: 16 rows x 128 cols
            float4 vb = *(const float4*)(Bm + (size_t)(k0 + rb) * FF + tile_n + cb);
            *(float4*)&Bs[rb][cb] = vb;
        }
        __syncthreads();
#pragma unroll
        for (int kk = 0; kk < BKK; kk++) {
            float a[TM], bb[TN];
#pragma unroll
            for (int i = 0; i < TM; i++) a[i] = As[kk][tm + i];
#pragma unroll
            for (int j = 0; j < TN; j++) bb[j] = Bs[kk][tn + j];
#pragma unroll
            for (int i = 0; i < TM; i++)
#pragma unroll
                for (int j = 0; j < TN; j++) acc[i][j] += a[i] * bb[j];
        }
        __syncthreads();
    }

    const float* bias = b1 + (size_t)e * FF + tile_n;
#pragma unroll
    for (int i = 0; i < TM; i++) {
        size_t row = (size_t)(tile_m + tm + i);
#pragma unroll
        for (int j = 0; j < TN; j++) {
            float v = acc[i][j] + bias[tn + j];
            v = 0.5f * v * (1.0f + erff(v * 0.70710678118654752f));  // exact gelu
            C[row * FF + tile_n + tn + j] = v;
        }
    }
}

// ---------------------------------------------------------------------------
// Kernel 4: out[b] = sum_k w[b,k] * (h[b,k] @ W2[e] + b2[e])
// Weight folded into the A smem load; both k-slots accumulated in one CTA.
// grid (DD/BN=8, TT/BM=16, B=8), block 256.
// ---------------------------------------------------------------------------
__global__ __launch_bounds__(NTHREADS, 2)
void gemm2_kernel(const float* __restrict__ W2, const float* __restrict__ b2,
                  float* __restrict__ out) {
    __shared__ float As[BKK][BM + 4];
    __shared__ float Bs[BKK][BN + 4];

    int b = blockIdx.z;
    int tile_m = blockIdx.y * BM;
    int tile_n = blockIdx.x * BN;
    int tid = threadIdx.x;
    int tm = (tid >> 4) * TM;
    int tn = (tid & 15) * TN;

    float acc[TM][TN];
#pragma unroll
    for (int i = 0; i < TM; i++)
#pragma unroll
        for (int j = 0; j < TN; j++) acc[i][j] = 0.0f;

    for (int k = 0; k < KK; k++) {
        int slot = 2 * b + k;
        int e = g_eidx[slot];
        float wgt = g_ew[slot];
        const float* A  = g_h + (size_t)slot * TT * FF;   // (2048,4096)
        const float* Bm = W2  + (size_t)e * FF * DD;      // (4096,1024)

        for (int k0 = 0; k0 < FF; k0 += BKK) {
#pragma unroll
            for (int i = 0; i < 2; i++) {
                int l = tid + i * NTHREADS;
                int r = l >> 2, c = (l & 3) * 4;
                float4 va = *(const float4*)(A + (size_t)(tile_m + r) * FF + k0 + c);
                As[c + 0][r] = wgt * va.x; As[c + 1][r] = wgt * va.y;
                As[c + 2][r] = wgt * va.z; As[c + 3][r] = wgt * va.w;
                int rb = l >> 5, cb = (l & 31) * 4;
                float4 vb = *(const float4*)(Bm + (size_t)(k0 + rb) * DD + tile_n + cb);
                *(float4*)&Bs[rb][cb] = vb;
            }
            __syncthreads();
#pragma unroll
            for (int kk = 0; kk < BKK; kk++) {
                float a[TM], bb[TN];
#pragma unroll
                for (int i = 0; i < TM; i++) a[i] = As[kk][tm + i];
#pragma unroll
                for (int j = 0; j < TN; j++) bb[j] = Bs[kk][tn + j];
#pragma unroll
                for (int i = 0; i < TM; i++)
#pragma unroll
                    for (int j = 0; j < TN; j++) acc[i][j] += a[i] * bb[j];
            }
            __syncthreads();
        }
    }

    int e0 = g_eidx[2 * b], e1 = g_eidx[2 * b + 1];
    float w0 = g_ew[2 * b], w1 = g_ew[2 * b + 1];
    const float* b20 = b2 + (size_t)e0 * DD + tile_n;
    const float* b21 = b2 + (size_t)e1 * DD + tile_n;
    float* O = out + (size_t)b * TT * DD;
#pragma unroll
    for (int i = 0; i < TM; i++) {
        size_t row = (size_t)(tile_m + tm + i);
#pragma unroll
        for (int j = 0; j < TN; j++) {
            float bias = w0 * b20[tn + j] + w1 * b21[tn + j];
            O[row * DD + tile_n + tn + j] = acc[i][j] + bias;
        }
    }
}

// ---------------------------------------------------------------------------
extern "C" void kernel_launch(void* const* d_in, const int* in_sizes, int n_in,
                              void* d_out, int out_size) {
    const float* x  = (const float*)d_in[0];
    const float* Wr = (const float*)d_in[1];
    const float* W1 = (const float*)d_in[2];
    const float* b1 = (const float*)d_in[3];
    const float* W2 = (const float*)d_in[4];
    const float* b2 = (const float*)d_in[5];
    float* out = (float*)d_out;

    pool_kernel<<<dim3(BB, DD / 256), 256>>>(x);
    route_kernel<<<1, 256>>>(Wr);
    gemm1_kernel<<<dim3(FF / BN, TT / BM, BB * KK), NTHREADS>>>(x, W1, b1);
    gemm2_kernel<<<dim3(DD / BN, TT / BM, BB), NTHREADS>>>(W2, b2, out);
}

// round 4
// speedup vs baseline: 1.7485x; 1.7485x over previous
#include <cuda_runtime.h>
#include <math.h>
#include <stdint.h>

#define BB 8
#define TT 2048
#define DD 1024
#define FF 4096
#define EE 8

#define BM 128
#define BN 256
#define BKT 16
#define NTH 256
#define LDA 20           // As row stride (u32 units), conflict-free frag loads
#define LDB 264          // Bs row stride (u32 units)

#define ASTAGE (BM * LDA)        // 2560 u32 = 10240 B
#define BSTAGE (BKT * LDB)       // 4224 u32 = 16896 B
#define SMEM_BYTES ((2 * ASTAGE + 2 * BSTAGE) * 4)   // 54272 B

// ---------------- device scratch (no allocation allowed) -------------------
__device__ float g_pooled[BB * DD];
__device__ int   g_eidx[BB * 2];
__device__ float g_ew[BB * 2];
__device__ float g_h[(size_t)BB * 2 * TT * FF];   // 512MB: w*gelu(x@W1+b1)

// ---------------- helpers ---------------------------------------------------
static __device__ __forceinline__ uint32_t f2tf(float f) {
    uint32_t r;
    asm("cvt.rna.tf32.f32 %0, %1;" : "=r"(r) : "f"(f));
    return r;
}
static __device__ __forceinline__ void mma8(float* c, const uint32_t* a, const uint32_t* b) {
    asm volatile(
        "mma.sync.aligned.m16n8k8.row.col.f32.tf32.tf32.f32 "
        "{%0,%1,%2,%3}, {%4,%5,%6,%7}, {%8,%9}, {%0,%1,%2,%3};"
        : "+f"(c[0]), "+f"(c[1]), "+f"(c[2]), "+f"(c[3])
        : "r"(a[0]), "r"(a[1]), "r"(a[2]), "r"(a[3]), "r"(b[0]), "r"(b[1]));
}

// Stage GMEM -> regs. A tile: BM x BKT (row-major, stride lda).
// B tile: BKT x BN (row-major, stride ldb).
static __device__ __forceinline__ void stage_ldg(
    const float* __restrict__ Asrc, int lda,
    const float* __restrict__ Bsrc, int ldb,
    int tid, float4 av[2], float4 bv[4])
{
#pragma unroll
    for (int i = 0; i < 2; i++) {
        int idx = i * NTH + tid;
        int m = idx >> 2, kq = idx & 3;
        av[i] = *(const float4*)(Asrc + (size_t)m * lda + kq * 4);
    }
#pragma unroll
    for (int i = 0; i < 4; i++) {
        int idx = i * NTH + tid;
        int k = idx >> 6, n4 = idx & 63;
        bv[i] = *(const float4*)(Bsrc + (size_t)k * ldb + n4 * 4);
    }
}

// Regs -> SMEM with tf32 rounding.  A col interleave within each k8 block:
// c -> (c&8) | ((c&3)<<1) | ((c>>2)&1), so (t, t+4) sit adjacent (LDS.64 pairs).
static __device__ __forceinline__ void stage_sts(
    uint32_t* __restrict__ as, uint32_t* __restrict__ bs,
    int tid, const float4 av[2], const float4 bv[4])
{
#pragma unroll
    for (int i = 0; i < 2; i++) {
        int idx = i * NTH + tid;
        int m = idx >> 2, kq = idx & 3;
        float v[4] = { av[i].x, av[i].y, av[i].z, av[i].w };
#pragma unroll
        for (int j = 0; j < 4; j++) {
            int c = kq * 4 + j;
            int cp = (c & 8) | ((c & 3) << 1) | ((c >> 2) & 1);
            as[m * LDA + cp] = f2tf(v[j]);
        }
    }
#pragma unroll
    for (int i = 0; i < 4; i++) {
        int idx = i * NTH + tid;
        int k = idx >> 6, n4 = idx & 63;
        uint4 u;
        u.x = f2tf(bv[i].x); u.y = f2tf(bv[i].y);
        u.z = f2tf(bv[i].z); u.w = f2tf(bv[i].w);
        *(uint4*)&bs[k * LDB + n4 * 4] = u;
    }
}

// Core mainloop: acc(128x256 per CTA) += [A0;A1] @ [B0;B1].
// Stage s uses source pair (s>=half ? 1 : 0) with local k0.
static __device__ __forceinline__ void gemm_core(
    const float* __restrict__ A0, const float* __restrict__ A1, int lda,
    const float* __restrict__ B0, const float* __restrict__ B1, int ldb,
    int nst, int half, uint32_t* smu, float acc[4][8][4])
{
    int tid = threadIdx.x;
    int wid = tid >> 5, lane = tid & 31;
    int wm = wid & 1, wn = wid >> 1;
    int g = lane >> 2, tig = lane & 3;

    uint32_t* asb[2] = { smu, smu + ASTAGE };
    uint32_t* bsb[2] = { smu + 2 * ASTAGE, smu + 2 * ASTAGE + BSTAGE };

    float4 av[2]; float4 bv[4];

    stage_ldg(A0, lda, B0, ldb, tid, av, bv);
    stage_sts(asb[0], bsb[0], tid, av, bv);
    __syncthreads();

    for (int s = 0; s < nst; s++) {
        int buf = s & 1;
        uint32_t* as = asb[buf];
        uint32_t* bs = bsb[buf];
        bool pre = (s + 1 < nst);
        if (pre) {
            int t = s + 1;
            int sel = (t >= half);
            int k0 = (t - (sel ? half : 0)) * BKT;
            stage_ldg((sel ? A1 : A0) + k0, lda,
                      (sel ? B1 : B0) + (size_t)k0 * ldb, ldb, tid, av, bv);
        }
#pragma unroll
        for (int ks = 0; ks < 2; ks++) {
            uint32_t a[4][4];
#pragma unroll
            for (int mi = 0; mi < 4; mi++) {
                int rb = wm * 64 + mi * 16;
                uint2 p0 = *(uint2*)&as[(rb + g) * LDA + ks * 8 + 2 * tig];
                uint2 p1 = *(uint2*)&as[(rb + g + 8) * LDA + ks * 8 + 2 * tig];
                a[mi][0] = p0.x; a[mi][2] = p0.y;
                a[mi][1] = p1.x; a[mi][3] = p1.y;
            }
#pragma unroll
            for (int ni = 0; ni < 8; ni++) {
                int n = wn * 64 + ni * 8 + g;
                uint32_t b[2];
                b[0] = bs[(ks * 8 + tig) * LDB + n];
                b[1] = bs[(ks * 8 + tig + 4) * LDB + n];
#pragma unroll
                for (int mi = 0; mi < 4; mi++) mma8(acc[mi][ni], a[mi], b);
            }
        }
        if (pre) {
            stage_sts(asb[buf ^ 1], bsb[buf ^ 1], tid, av, bv);
            __syncthreads();
        }
    }
}

// ---------------- Kernel 1: mean pool ---------------------------------------
__global__ void pool_kernel(const float* __restrict__ x) {
    int b = blockIdx.x;
    int d = blockIdx.y * blockDim.x + threadIdx.x;
    const float* xp = x + (size_t)b * TT * DD + d;
    float s = 0.0f;
#pragma unroll 8
    for (int t = 0; t < TT; t++) s += xp[(size_t)t * DD];
    g_pooled[b * DD + d] = s * (1.0f / (float)TT);
}

// ---------------- Kernel 2: routing -----------------------------------------
__global__ void route_kernel(const float* __restrict__ Wr) {
    int w = threadIdx.x >> 5;
    int lane = threadIdx.x & 31;
    if (w >= BB) return;
    float sums[EE];
#pragma unroll
    for (int e = 0; e < EE; e++) sums[e] = 0.0f;
    for (int d = lane; d < DD; d += 32) {
        float p = g_pooled[w * DD + d];
        const float* wr = Wr + d * EE;
#pragma unroll
        for (int e = 0; e < EE; e++) sums[e] += p * wr[e];
    }
#pragma unroll
    for (int e = 0; e < EE; e++)
#pragma unroll
        for (int off = 16; off > 0; off >>= 1)
            sums[e] += __shfl_xor_sync(0xFFFFFFFFu, sums[e], off);
    if (lane == 0) {
        int i0 = 0; float v0 = sums[0];
#pragma unroll
        for (int e = 1; e < EE; e++) if (sums[e] > v0) { v0 = sums[e]; i0 = e; }
        int i1 = -1; float v1 = -1e30f;
#pragma unroll
        for (int e = 0; e < EE; e++) {
            if (e == i0) continue;
            if (sums[e] > v1) { v1 = sums[e]; i1 = e; }
        }
        float e1 = expf(v1 - v0);
        float inv = 1.0f / (1.0f + e1);
        g_eidx[2 * w + 0] = i0;  g_eidx[2 * w + 1] = i1;
        g_ew[2 * w + 0] = inv;   g_ew[2 * w + 1] = e1 * inv;
    }
}

// ---------------- Kernel 3: GEMM1  h = w * gelu(x @ W1 + b1) ----------------
__global__ __launch_bounds__(NTH, 1)
void moe_gemm1(const float* __restrict__ x, const float* __restrict__ W1p,
               const float* __restrict__ b1p) {
    extern __shared__ uint32_t smu[];
    int slot = blockIdx.z, b = slot >> 1;
    int e = g_eidx[slot];
    float wgt = g_ew[slot];
    int tile_m = blockIdx.y * BM, tile_n = blockIdx.x * BN;

    const float* A  = x   + (size_t)b * TT * DD + (size_t)tile_m * DD;
    const float* Bp = W1p + (size_t)e * DD * FF + tile_n;

    float acc[4][8][4];
#pragma unroll
    for (int i = 0; i < 4; i++)
#pragma unroll
        for (int j = 0; j < 8; j++)
#pragma unroll
            for (int q = 0; q < 4; q++) acc[i][j][q] = 0.0f;

    gemm_core(A, A, DD, Bp, Bp, FF, DD / BKT, DD / BKT, smu, acc);

    int lane = threadIdx.x & 31, wid = threadIdx.x >> 5;
    int wm = wid & 1, wn = wid >> 1;
    int g = lane >> 2, tig = lane & 3;
    const float* bp = b1p + (size_t)e * FF + tile_n;
    float* C = g_h + ((size_t)slot * TT + tile_m) * FF + tile_n;
#pragma unroll
    for (int mi = 0; mi < 4; mi++) {
#pragma unroll
        for (int h2 = 0; h2 < 2; h2++) {
            int row = wm * 64 + mi * 16 + g + h2 * 8;
            float* Crow = C + (size_t)row * FF;
#pragma unroll
            for (int ni = 0; ni < 8; ni++) {
                int col = wn * 64 + ni * 8 + 2 * tig;
                float v0 = acc[mi][ni][h2 * 2 + 0] + bp[col];
                float v1 = acc[mi][ni][h2 * 2 + 1] + bp[col + 1];
                float2 o;
                o.x = wgt * 0.5f * v0 * (1.0f + erff(v0 * 0.70710678118654752f));
                o.y = wgt * 0.5f * v1 * (1.0f + erff(v1 * 0.70710678118654752f));
                *(float2*)(Crow + col) = o;
            }
        }
    }
}

// ---------------- Kernel 4: GEMM2  out = h0@W2[e0] + h1@W2[e1] + wbias ------
__global__ __launch_bounds__(NTH, 1)
void moe_gemm2(const float* __restrict__ W2p, const float* __restrict__ b2p,
               float* __restrict__ out) {
    extern __shared__ uint32_t smu[];
    int b = blockIdx.z;
    int e0 = g_eidx[2 * b], e1 = g_eidx[2 * b + 1];
    float w0 = g_ew[2 * b], w1 = g_ew[2 * b + 1];
    int tile_m = blockIdx.y * BM, tile_n = blockIdx.x * BN;

    const float* A0 = g_h + ((size_t)(2 * b + 0) * TT + tile_m) * FF;
    const float* A1 = g_h + ((size_t)(2 * b + 1) * TT + tile_m) * FF;
    const float* B0 = W2p + (size_t)e0 * FF * DD + tile_n;
    const float* B1 = W2p + (size_t)e1 * FF * DD + tile_n;

    float acc[4][8][4];
#pragma unroll
    for (int i = 0; i < 4; i++)
#pragma unroll
        for (int j = 0; j < 8; j++)
#pragma unroll
            for (int q = 0; q < 4; q++) acc[i][j][q] = 0.0f;

    gemm_core(A0, A1, FF, B0, B1, DD, 2 * FF / BKT, FF / BKT, smu, acc);

    int lane = threadIdx.x & 31, wid = threadIdx.x >> 5;
    int wm = wid & 1, wn = wid >> 1;
    int g = lane >> 2, tig = lane & 3;
    const float* bp0 = b2p + (size_t)e0 * DD + tile_n;
    const float* bp1 = b2p + (size_t)e1 * DD + tile_n;
    float* C = out + ((size_t)b * TT + tile_m) * DD + tile_n;
#pragma unroll
    for (int mi = 0; mi < 4; mi++) {
#pragma unroll
        for (int h2 = 0; h2 < 2; h2++) {
            int row = wm * 64 + mi * 16 + g + h2 * 8;
            float* Crow = C + (size_t)row * DD;
#pragma unroll
            for (int ni = 0; ni < 8; ni++) {
                int col = wn * 64 + ni * 8 + 2 * tig;
                float2 o;
                o.x = acc[mi][ni][h2 * 2 + 0] + w0 * bp0[col]     + w1 * bp1[col];
                o.y = acc[mi][ni][h2 * 2 + 1] + w0 * bp0[col + 1] + w1 * bp1[col + 1];
                *(float2*)(Crow + col) = o;
            }
        }
    }
}

// ---------------------------------------------------------------------------
extern "C" void kernel_launch(void* const* d_in, const int* in_sizes, int n_in,
                              void* d_out, int out_size) {
    const float* x  = (const float*)d_in[0];
    const float* Wr = (const float*)d_in[1];
    const float* W1 = (const float*)d_in[2];
    const float* b1 = (const float*)d_in[3];
    const float* W2 = (const float*)d_in[4];
    const float* b2 = (const float*)d_in[5];
    float* out = (float*)d_out;

    static int inited = 0;
    if (!inited) {
        cudaFuncSetAttribute(moe_gemm1, cudaFuncAttributeMaxDynamicSharedMemorySize, SMEM_BYTES);
        cudaFuncSetAttribute(moe_gemm2, cudaFuncAttributeMaxDynamicSharedMemorySize, SMEM_BYTES);
        inited = 1;
    }

    pool_kernel<<<dim3(BB, DD / 256), 256>>>(x);
    route_kernel<<<1, 256>>>(Wr);
    moe_gemm1<<<dim3(FF / BN, TT / BM, BB * 2), NTH, SMEM_BYTES>>>(x, W1, b1);
    moe_gemm2<<<dim3(DD / BN, TT / BM, BB), NTH, SMEM_BYTES>>>(W2, b2, out);
}

// round 5
// speedup vs baseline: 1.9352x; 1.1068x over previous
#include <cuda_runtime.h>
#include <math.h>
#include <stdint.h>

#define BB 8
#define TT 2048
#define DD 1024
#define FF 4096
#define EE 8

#define BM 128
#define BN 256
#define BKT 16
#define NTH 512
#define LDA 20           // As row stride (u32 units), conflict-free frag loads
#define LDB 264          // Bs row stride (u32 units)

#define ASTAGE (BM * LDA)        // 2560 u32 = 10240 B
#define BSTAGE (BKT * LDB)       // 4224 u32 = 16896 B
#define SMEM_BYTES ((2 * ASTAGE + 2 * BSTAGE) * 4)   // 54272 B

// ---------------- device scratch (no allocation allowed) -------------------
__device__ float g_pooled[BB * DD];
__device__ int   g_eidx[BB * 2];
__device__ float g_ew[BB * 2];
__device__ float g_h[(size_t)BB * 2 * TT * FF];   // 512MB: w*gelu(x@W1+b1)

// ---------------- helpers ---------------------------------------------------
static __device__ __forceinline__ uint32_t f2tf(float f) {
    uint32_t r;
    asm("cvt.rna.tf32.f32 %0, %1;" : "=r"(r) : "f"(f));
    return r;
}
static __device__ __forceinline__ void mma8(float* c, const uint32_t* a, const uint32_t* b) {
    asm volatile(
        "mma.sync.aligned.m16n8k8.row.col.f32.tf32.tf32.f32 "
        "{%0,%1,%2,%3}, {%4,%5,%6,%7}, {%8,%9}, {%0,%1,%2,%3};"
        : "+f"(c[0]), "+f"(c[1]), "+f"(c[2]), "+f"(c[3])
        : "r"(a[0]), "r"(a[1]), "r"(a[2]), "r"(a[3]), "r"(b[0]), "r"(b[1]));
}

// Stage GMEM -> regs. A tile: BM x BKT (row-major, stride lda).
// B tile: BKT x BN (row-major, stride ldb).  512 threads.
static __device__ __forceinline__ void stage_ldg(
    const float* __restrict__ Asrc, int lda,
    const float* __restrict__ Bsrc, int ldb,
    int tid, float4& av, float4 bv[2])
{
    {
        int m = tid >> 2, kq = tid & 3;                 // 128 x 4 quads
        av = *(const float4*)(Asrc + (size_t)m * lda + kq * 4);
    }
#pragma unroll
    for (int i = 0; i < 2; i++) {
        int idx = i * NTH + tid;
        int k = idx >> 6, n4 = idx & 63;                // 16 x 64 quads
        bv[i] = *(const float4*)(Bsrc + (size_t)k * ldb + n4 * 4);
    }
}

// Regs -> SMEM with tf32 rounding.  A col interleave within each k8 block:
// c -> (c&8) | ((c&3)<<1) | ((c>>2)&1), so (t, t+4) sit adjacent (LDS.64 pairs).
static __device__ __forceinline__ void stage_sts(
    uint32_t* __restrict__ as, uint32_t* __restrict__ bs,
    int tid, const float4& av, const float4 bv[2])
{
    {
        int m = tid >> 2, kq = tid & 3;
        float v[4] = { av.x, av.y, av.z, av.w };
#pragma unroll
        for (int j = 0; j < 4; j++) {
            int c = kq * 4 + j;
            int cp = (c & 8) | ((c & 3) << 1) | ((c >> 2) & 1);
            as[m * LDA + cp] = f2tf(v[j]);
        }
    }
#pragma unroll
    for (int i = 0; i < 2; i++) {
        int idx = i * NTH + tid;
        int k = idx >> 6, n4 = idx & 63;
        uint4 u;
        u.x = f2tf(bv[i].x); u.y = f2tf(bv[i].y);
        u.z = f2tf(bv[i].z); u.w = f2tf(bv[i].w);
        *(uint4*)&bs[k * LDB + n4 * 4] = u;
    }
}

// Core mainloop: acc(128x256 per CTA) += [A0;A1] @ [B0;B1].
// 16 warps: wm = wid&1 (64 rows), wn = wid>>1 (32 cols). acc[4][4][4].
static __device__ __forceinline__ void gemm_core(
    const float* __restrict__ A0, const float* __restrict__ A1, int lda,
    const float* __restrict__ B0, const float* __restrict__ B1, int ldb,
    int nst, int half, uint32_t* smu, float acc[4][4][4])
{
    int tid = threadIdx.x;
    int wid = tid >> 5, lane = tid & 31;
    int wm = wid & 1, wn = wid >> 1;
    int g = lane >> 2, tig = lane & 3;

    uint32_t* asb[2] = { smu, smu + ASTAGE };
    uint32_t* bsb[2] = { smu + 2 * ASTAGE, smu + 2 * ASTAGE + BSTAGE };

    float4 av; float4 bv[2];

    stage_ldg(A0, lda, B0, ldb, tid, av, bv);
    stage_sts(asb[0], bsb[0], tid, av, bv);
    __syncthreads();

    for (int s = 0; s < nst; s++) {
        int buf = s & 1;
        uint32_t* as = asb[buf];
        uint32_t* bs = bsb[buf];
        bool pre = (s + 1 < nst);
        if (pre) {
            int t = s + 1;
            int sel = (t >= half);
            int k0 = (t - (sel ? half : 0)) * BKT;
            stage_ldg((sel ? A1 : A0) + k0, lda,
                      (sel ? B1 : B0) + (size_t)k0 * ldb, ldb, tid, av, bv);
        }
#pragma unroll
        for (int ks = 0; ks < 2; ks++) {
            uint32_t a[4][4];
#pragma unroll
            for (int mi = 0; mi < 4; mi++) {
                int rb = wm * 64 + mi * 16;
                uint2 p0 = *(uint2*)&as[(rb + g) * LDA + ks * 8 + 2 * tig];
                uint2 p1 = *(uint2*)&as[(rb + g + 8) * LDA + ks * 8 + 2 * tig];
                a[mi][0] = p0.x; a[mi][2] = p0.y;
                a[mi][1] = p1.x; a[mi][3] = p1.y;
            }
#pragma unroll
            for (int ni = 0; ni < 4; ni++) {
                int n = wn * 32 + ni * 8 + g;
                uint32_t b[2];
                b[0] = bs[(ks * 8 + tig) * LDB + n];
                b[1] = bs[(ks * 8 + tig + 4) * LDB + n];
#pragma unroll
                for (int mi = 0; mi < 4; mi++) mma8(acc[mi][ni], a[mi], b);
            }
        }
        if (pre) {
            stage_sts(asb[buf ^ 1], bsb[buf ^ 1], tid, av, bv);
            __syncthreads();
        }
    }
}

// ---------------- Kernel 1: mean pool ---------------------------------------
__global__ void pool_kernel(const float* __restrict__ x) {
    int b = blockIdx.x;
    int d = blockIdx.y * blockDim.x + threadIdx.x;
    const float* xp = x + (size_t)b * TT * DD + d;
    float s = 0.0f;
#pragma unroll 8
    for (int t = 0; t < TT; t++) s += xp[(size_t)t * DD];
    g_pooled[b * DD + d] = s * (1.0f / (float)TT);
}

// ---------------- Kernel 2: routing -----------------------------------------
__global__ void route_kernel(const float* __restrict__ Wr) {
    int w = threadIdx.x >> 5;
    int lane = threadIdx.x & 31;
    if (w >= BB) return;
    float sums[EE];
#pragma unroll
    for (int e = 0; e < EE; e++) sums[e] = 0.0f;
    for (int d = lane; d < DD; d += 32) {
        float p = g_pooled[w * DD + d];
        const float* wr = Wr + d * EE;
#pragma unroll
        for (int e = 0; e < EE; e++) sums[e] += p * wr[e];
    }
#pragma unroll
    for (int e = 0; e < EE; e++)
#pragma unroll
        for (int off = 16; off > 0; off >>= 1)
            sums[e] += __shfl_xor_sync(0xFFFFFFFFu, sums[e], off);
    if (lane == 0) {
        int i0 = 0; float v0 = sums[0];
#pragma unroll
        for (int e = 1; e < EE; e++) if (sums[e] > v0) { v0 = sums[e]; i0 = e; }
        int i1 = -1; float v1 = -1e30f;
#pragma unroll
        for (int e = 0; e < EE; e++) {
            if (e == i0) continue;
            if (sums[e] > v1) { v1 = sums[e]; i1 = e; }
        }
        float e1 = expf(v1 - v0);
        float inv = 1.0f / (1.0f + e1);
        g_eidx[2 * w + 0] = i0;  g_eidx[2 * w + 1] = i1;
        g_ew[2 * w + 0] = inv;   g_ew[2 * w + 1] = e1 * inv;
    }
}

// ---------------- Kernel 3: GEMM1  h = w * gelu(x @ W1 + b1) ----------------
__global__ __launch_bounds__(NTH, 1)
void moe_gemm1(const float* __restrict__ x, const float* __restrict__ W1p,
               const float* __restrict__ b1p) {
    extern __shared__ uint32_t smu[];
    int slot = blockIdx.z, b = slot >> 1;
    int e = g_eidx[slot];
    float wgt = g_ew[slot];
    int tile_m = blockIdx.y * BM, tile_n = blockIdx.x * BN;

    const float* A  = x   + (size_t)b * TT * DD + (size_t)tile_m * DD;
    const float* Bp = W1p + (size_t)e * DD * FF + tile_n;

    float acc[4][4][4];
#pragma unroll
    for (int i = 0; i < 4; i++)
#pragma unroll
        for (int j = 0; j < 4; j++)
#pragma unroll
            for (int q = 0; q < 4; q++) acc[i][j][q] = 0.0f;

    gemm_core(A, A, DD, Bp, Bp, FF, DD / BKT, DD / BKT, smu, acc);

    int lane = threadIdx.x & 31, wid = threadIdx.x >> 5;
    int wm = wid & 1, wn = wid >> 1;
    int g = lane >> 2, tig = lane & 3;
    const float* bp = b1p + (size_t)e * FF + tile_n;
    float* C = g_h + ((size_t)slot * TT + tile_m) * FF + tile_n;
#pragma unroll
    for (int mi = 0; mi < 4; mi++) {
#pragma unroll
        for (int h2 = 0; h2 < 2; h2++) {
            int row = wm * 64 + mi * 16 + g + h2 * 8;
            float* Crow = C + (size_t)row * FF;
#pragma unroll
            for (int ni = 0; ni < 4; ni++) {
                int col = wn * 32 + ni * 8 + 2 * tig;
                float v0 = acc[mi][ni][h2 * 2 + 0] + bp[col];
                float v1 = acc[mi][ni][h2 * 2 + 1] + bp[col + 1];
                float2 o;
                o.x = wgt * 0.5f * v0 * (1.0f + erff(v0 * 0.70710678118654752f));
                o.y = wgt * 0.5f * v1 * (1.0f + erff(v1 * 0.70710678118654752f));
                *(float2*)(Crow + col) = o;
            }
        }
    }
}

// ---------------- Kernel 4: GEMM2  out = h0@W2[e0] + h1@W2[e1] + wbias ------
__global__ __launch_bounds__(NTH, 1)
void moe_gemm2(const float* __restrict__ W2p, const float* __restrict__ b2p,
               float* __restrict__ out) {
    extern __shared__ uint32_t smu[];
    int b = blockIdx.z;
    int e0 = g_eidx[2 * b], e1 = g_eidx[2 * b + 1];
    float w0 = g_ew[2 * b], w1 = g_ew[2 * b + 1];
    int tile_m = blockIdx.y * BM, tile_n = blockIdx.x * BN;

    const float* A0 = g_h + ((size_t)(2 * b + 0) * TT + tile_m) * FF;
    const float* A1 = g_h + ((size_t)(2 * b + 1) * TT + tile_m) * FF;
    const float* B0 = W2p + (size_t)e0 * FF * DD + tile_n;
    const float* B1 = W2p + (size_t)e1 * FF * DD + tile_n;

    float acc[4][4][4];
#pragma unroll
    for (int i = 0; i < 4; i++)
#pragma unroll
        for (int j = 0; j < 4; j++)
#pragma unroll
            for (int q = 0; q < 4; q++) acc[i][j][q] = 0.0f;

    gemm_core(A0, A1, FF, B0, B1, DD, 2 * FF / BKT, FF / BKT, smu, acc);

    int lane = threadIdx.x & 31, wid = threadIdx.x >> 5;
    int wm = wid & 1, wn = wid >> 1;
    int g = lane >> 2, tig = lane & 3;
    const float* bp0 = b2p + (size_t)e0 * DD + tile_n;
    const float* bp1 = b2p + (size_t)e1 * DD + tile_n;
    float* C = out + ((size_t)b * TT + tile_m) * DD + tile_n;
#pragma unroll
    for (int mi = 0; mi < 4; mi++) {
#pragma unroll
        for (int h2 = 0; h2 < 2; h2++) {
            int row = wm * 64 + mi * 16 + g + h2 * 8;
            float* Crow = C + (size_t)row * DD;
#pragma unroll
            for (int ni = 0; ni < 4; ni++) {
                int col = wn * 32 + ni * 8 + 2 * tig;
                float2 o;
                o.x = acc[mi][ni][h2 * 2 + 0] + w0 * bp0[col]     + w1 * bp1[col];
                o.y = acc[mi][ni][h2 * 2 + 1] + w0 * bp0[col + 1] + w1 * bp1[col + 1];
                *(float2*)(Crow + col) = o;
            }
        }
    }
}

// ---------------------------------------------------------------------------
extern "C" void kernel_launch(void* const* d_in, const int* in_sizes, int n_in,
                              void* d_out, int out_size) {
    const float* x  = (const float*)d_in[0];
    const float* Wr = (const float*)d_in[1];
    const float* W1 = (const float*)d_in[2];
    const float* b1 = (const float*)d_in[3];
    const float* W2 = (const float*)d_in[4];
    const float* b2 = (const float*)d_in[5];
    float* out = (float*)d_out;

    static int inited = 0;
    if (!inited) {
        cudaFuncSetAttribute(moe_gemm1, cudaFuncAttributeMaxDynamicSharedMemorySize, SMEM_BYTES);
        cudaFuncSetAttribute(moe_gemm2, cudaFuncAttributeMaxDynamicSharedMemorySize, SMEM_BYTES);
        inited = 1;
    }

    pool_kernel<<<dim3(BB, DD / 256), 256>>>(x);
    route_kernel<<<1, 256>>>(Wr);
    moe_gemm1<<<dim3(FF / BN, TT / BM, BB * 2), NTH, SMEM_BYTES>>>(x, W1, b1);
    moe_gemm2<<<dim3(DD / BN, TT / BM, BB), NTH, SMEM_BYTES>>>(W2, b2, out);
}

// round 6
// speedup vs baseline: 1.9712x; 1.0186x over previous
#include <cuda_runtime.h>
#include <math.h>
#include <stdint.h>

#define BB 8
#define TT 2048
#define DD 1024
#define FF 4096
#define EE 8

#define BM 128
#define BN 256
#define BKT 32
#define NTH 512
#define LDAU 32          // A smem row stride (u32): 128B rows, XOR-swizzled chunks
#define LDBU 264         // B smem row stride (u32)

#define ASTG (BM * LDAU)     // 4096 u32 = 16KB
#define BSTG (BKT * LDBU)    // 8448 u32 = 33792B
#define SMEM_BYTES ((2 * ASTG + 2 * BSTG) * 4)   // 100352 B

// ---------------- device scratch (no allocation allowed) -------------------
__device__ float g_pooled[BB * DD];
__device__ int   g_eidx[BB * 2];
__device__ float g_ew[BB * 2];
__device__ float g_xr[(size_t)BB * TT * DD];      // 64MB: tf32-rounded x
__device__ float g_h[(size_t)BB * 2 * TT * FF];   // 512MB: tf32(w*gelu(x@W1+b1))

// ---------------- helpers ---------------------------------------------------
static __device__ __forceinline__ uint32_t smem_u32(const void* p) {
    uint32_t a;
    asm("{ .reg .u64 t; cvta.to.shared.u64 t, %1; cvt.u32.u64 %0, t; }" : "=r"(a) : "l"(p));
    return a;
}
static __device__ __forceinline__ uint32_t f2tf(float f) {
    uint32_t r;
    asm("cvt.rna.tf32.f32 %0, %1;" : "=r"(r) : "f"(f));
    return r;
}
static __device__ __forceinline__ void mma8(float* c, const uint32_t* a, const uint32_t* b) {
    asm volatile(
        "mma.sync.aligned.m16n8k8.row.col.f32.tf32.tf32.f32 "
        "{%0,%1,%2,%3}, {%4,%5,%6,%7}, {%8,%9}, {%0,%1,%2,%3};"
        : "+f"(c[0]), "+f"(c[1]), "+f"(c[2]), "+f"(c[3])
        : "r"(a[0]), "r"(a[1]), "r"(a[2]), "r"(a[3]), "r"(b[0]), "r"(b[1]));
}
static __device__ __forceinline__ void cpa16(uint32_t dst, const float* src) {
    asm volatile("cp.async.cg.shared.global [%0], [%1], 16;" :: "r"(dst), "l"(src));
}
static __device__ __forceinline__ void cpa_commit() {
    asm volatile("cp.async.commit_group;" ::: "memory");
}
static __device__ __forceinline__ void cpa_wait0() {
    asm volatile("cp.async.wait_group 0;" ::: "memory");
}

// A stage via cp.async: 128 rows x 32 k, 16B chunks XOR-swizzled by row&7.
static __device__ __forceinline__ void cpa_A(uint32_t asb, const float* __restrict__ Asrc,
                                             int lda, int tid) {
#pragma unroll
    for (int it = 0; it < 2; it++) {
        int r = (tid >> 3) + it * 64;
        int c = tid & 7;
        uint32_t dst = asb + (uint32_t)(r * LDAU + ((c ^ (r & 7)) << 2)) * 4u;
        cpa16(dst, Asrc + (size_t)r * lda + c * 4);
    }
}

// B stage: LDG 4 float4/thread (32 k x 256 n tile).
static __device__ __forceinline__ void ldg_B(const float* __restrict__ Bsrc, int ldb,
                                             int tid, float4 bv[4]) {
#pragma unroll
    for (int it = 0; it < 4; it++) {
        int idx = it * NTH + tid;
        int k = idx >> 6, n4 = idx & 63;
        bv[it] = *(const float4*)(Bsrc + (size_t)k * ldb + n4 * 4);
    }
}
// STS with tf32 rounding + column permutation n' = (n&~31)|((n&7)<<2)|((n>>3)&3)
static __device__ __forceinline__ void sts_B(uint32_t* __restrict__ bs, int tid,
                                             const float4 bv[4]) {
#pragma unroll
    for (int it = 0; it < 4; it++) {
        int idx = it * NTH + tid;
        int k = idx >> 6, n4 = idx & 63;
        float v[4] = { bv[it].x, bv[it].y, bv[it].z, bv[it].w };
#pragma unroll
        for (int j = 0; j < 4; j++) {
            int n = n4 * 4 + j;
            int np = (n & ~31) | ((n & 7) << 2) | ((n >> 3) & 3);
            bs[k * LDBU + np] = f2tf(v[j]);
        }
    }
}

// Compute 32-k block: 4 k8 sub-steps. A frags LDS.32 (swizzled), B frags LDS.128.
static __device__ __forceinline__ void compute32(const uint32_t* __restrict__ as,
                                                 const uint32_t* __restrict__ bs,
                                                 float acc[4][4][4],
                                                 int wm, int wn, int g, int tig) {
#pragma unroll
    for (int ks = 0; ks < 4; ks++) {
        uint32_t a[4][4];
        int c0 = (((2 * ks) ^ g) << 2) + tig;
        int c1 = (((2 * ks + 1) ^ g) << 2) + tig;
#pragma unroll
        for (int mi = 0; mi < 4; mi++) {
            int r0 = (wm * 64 + mi * 16 + g) * LDAU;
            a[mi][0] = as[r0 + c0];
            a[mi][2] = as[r0 + c1];
            a[mi][1] = as[r0 + 8 * LDAU + c0];
            a[mi][3] = as[r0 + 8 * LDAU + c1];
        }
        uint4 q0 = *(const uint4*)&bs[(ks * 8 + tig) * LDBU + wn * 32 + g * 4];
        uint4 q1 = *(const uint4*)&bs[(ks * 8 + tig + 4) * LDBU + wn * 32 + g * 4];
        uint32_t b0[4] = { q0.x, q0.y, q0.z, q0.w };
        uint32_t b1[4] = { q1.x, q1.y, q1.z, q1.w };
#pragma unroll
        for (int ni = 0; ni < 4; ni++) {
            uint32_t bb[2] = { b0[ni], b1[ni] };
#pragma unroll
            for (int mi = 0; mi < 4; mi++) mma8(acc[mi][ni], a[mi], bb);
        }
    }
}

// Mainloop: acc(128x256) += [A0;A1] @ [B0;B1]. A via cp.async, B via reg-stage.
static __device__ __forceinline__ void gemm_core(
    const float* __restrict__ A0, const float* __restrict__ A1, int lda,
    const float* __restrict__ B0, const float* __restrict__ B1, int ldb,
    int nst, int half, uint32_t* smu, float acc[4][4][4])
{
    int tid = threadIdx.x;
    int wid = tid >> 5, lane = tid & 31;
    int wm = wid & 1, wn = wid >> 1;
    int g = lane >> 2, tig = lane & 3;

    uint32_t* asb[2] = { smu, smu + ASTG };
    uint32_t* bsb[2] = { smu + 2 * ASTG, smu + 2 * ASTG + BSTG };
    uint32_t asbb[2] = { smem_u32(asb[0]), smem_u32(asb[1]) };

    float4 bv[4];

    // prologue: stage 0
    cpa_A(asbb[0], A0, lda, tid);
    cpa_commit();
    ldg_B(B0, ldb, tid, bv);
    sts_B(bsb[0], tid, bv);
    cpa_wait0();
    __syncthreads();

    for (int s = 0; s < nst; s++) {
        int buf = s & 1;
        bool pre = (s + 1 < nst);
        if (pre) {
            int t = s + 1;
            int sel = (t >= half);
            int k0 = (t - (sel ? half : 0)) * BKT;
            cpa_A(asbb[buf ^ 1], (sel ? A1 : A0) + k0, lda, tid);
            cpa_commit();
            ldg_B((sel ? B1 : B0) + (size_t)k0 * ldb, ldb, tid, bv);
        }
        compute32(asb[buf], bsb[buf], acc, wm, wn, g, tig);
        if (pre) {
            sts_B(bsb[buf ^ 1], tid, bv);
            cpa_wait0();
            __syncthreads();
        }
    }
}

// ---------------- Kernel 0: tf32 pre-round of x ------------------------------
__global__ void prep_kernel(const float* __restrict__ x) {
    size_t i = (size_t)blockIdx.x * blockDim.x + threadIdx.x;
    const float4* src = (const float4*)x;
    float4* dst = (float4*)g_xr;
    float4 v = src[i];
    float4 o;
    o.x = __uint_as_float(f2tf(v.x));
    o.y = __uint_as_float(f2tf(v.y));
    o.z = __uint_as_float(f2tf(v.z));
    o.w = __uint_as_float(f2tf(v.w));
    dst[i] = o;
}

// ---------------- Kernel 1: mean pool ---------------------------------------
__global__ void pool_kernel(const float* __restrict__ x) {
    int b = blockIdx.x;
    int d = blockIdx.y * blockDim.x + threadIdx.x;
    const float* xp = x + (size_t)b * TT * DD + d;
    float s = 0.0f;
#pragma unroll 8
    for (int t = 0; t < TT; t++) s += xp[(size_t)t * DD];
    g_pooled[b * DD + d] = s * (1.0f / (float)TT);
}

// ---------------- Kernel 2: routing -----------------------------------------
__global__ void route_kernel(const float* __restrict__ Wr) {
    int w = threadIdx.x >> 5;
    int lane = threadIdx.x & 31;
    if (w >= BB) return;
    float sums[EE];
#pragma unroll
    for (int e = 0; e < EE; e++) sums[e] = 0.0f;
    for (int d = lane; d < DD; d += 32) {
        float p = g_pooled[w * DD + d];
        const float* wr = Wr + d * EE;
#pragma unroll
        for (int e = 0; e < EE; e++) sums[e] += p * wr[e];
    }
#pragma unroll
    for (int e = 0; e < EE; e++)
#pragma unroll
        for (int off = 16; off > 0; off >>= 1)
            sums[e] += __shfl_xor_sync(0xFFFFFFFFu, sums[e], off);
    if (lane == 0) {
        int i0 = 0; float v0 = sums[0];
#pragma unroll
        for (int e = 1; e < EE; e++) if (sums[e] > v0) { v0 = sums[e]; i0 = e; }
        int i1 = -1; float v1 = -1e30f;
#pragma unroll
        for (int e = 0; e < EE; e++) {
            if (e == i0) continue;
            if (sums[e] > v1) { v1 = sums[e]; i1 = e; }
        }
        float e1 = expf(v1 - v0);
        float inv = 1.0f / (1.0f + e1);
        g_eidx[2 * w + 0] = i0;  g_eidx[2 * w + 1] = i1;
        g_ew[2 * w + 0] = inv;   g_ew[2 * w + 1] = e1 * inv;
    }
}

// ---------------- Kernel 3: GEMM1  h = tf32(w * gelu(x @ W1 + b1)) ----------
__global__ __launch_bounds__(NTH, 1)
void moe_gemm1(const float* __restrict__ W1p, const float* __restrict__ b1p) {
    extern __shared__ uint32_t smu[];
    int slot = blockIdx.z, b = slot >> 1;
    int e = g_eidx[slot];
    float wgt = g_ew[slot];
    int tile_m = blockIdx.y * BM, tile_n = blockIdx.x * BN;

    const float* A  = g_xr + (size_t)b * TT * DD + (size_t)tile_m * DD;
    const float* Bp = W1p  + (size_t)e * DD * FF + tile_n;

    float acc[4][4][4];
#pragma unroll
    for (int i = 0; i < 4; i++)
#pragma unroll
        for (int j = 0; j < 4; j++)
#pragma unroll
            for (int q = 0; q < 4; q++) acc[i][j][q] = 0.0f;

    gemm_core(A, A, DD, Bp, Bp, FF, DD / BKT, DD / BKT, smu, acc);

    int lane = threadIdx.x & 31, wid = threadIdx.x >> 5;
    int wm = wid & 1, wn = wid >> 1;
    int g = lane >> 2, tig = lane & 3;
    const float* bp = b1p + (size_t)e * FF + tile_n;
    float* C = g_h + ((size_t)slot * TT + tile_m) * FF + tile_n;
#pragma unroll
    for (int mi = 0; mi < 4; mi++) {
#pragma unroll
        for (int h2 = 0; h2 < 2; h2++) {
            int row = wm * 64 + mi * 16 + g + h2 * 8;
            float* Crow = C + (size_t)row * FF;
#pragma unroll
            for (int ni = 0; ni < 4; ni++) {
                int col = wn * 32 + ni * 8 + 2 * tig;
                float v0 = acc[mi][ni][h2 * 2 + 0] + bp[col];
                float v1 = acc[mi][ni][h2 * 2 + 1] + bp[col + 1];
                float2 o;
                o.x = __uint_as_float(f2tf(wgt * 0.5f * v0 * (1.0f + erff(v0 * 0.70710678118654752f))));
                o.y = __uint_as_float(f2tf(wgt * 0.5f * v1 * (1.0f + erff(v1 * 0.70710678118654752f))));
                *(float2*)(Crow + col) = o;
            }
        }
    }
}

// ---------------- Kernel 4: GEMM2  out = h0@W2[e0] + h1@W2[e1] + wbias ------
__global__ __launch_bounds__(NTH, 1)
void moe_gemm2(const float* __restrict__ W2p, const float* __restrict__ b2p,
               float* __restrict__ out) {
    extern __shared__ uint32_t smu[];
    int b = blockIdx.z;
    int e0 = g_eidx[2 * b], e1 = g_eidx[2 * b + 1];
    float w0 = g_ew[2 * b], w1 = g_ew[2 * b + 1];
    int tile_m = blockIdx.y * BM, tile_n = blockIdx.x * BN;

    const float* A0 = g_h + ((size_t)(2 * b + 0) * TT + tile_m) * FF;
    const float* A1 = g_h + ((size_t)(2 * b + 1) * TT + tile_m) * FF;
    const float* B0 = W2p + (size_t)e0 * FF * DD + tile_n;
    const float* B1 = W2p + (size_t)e1 * FF * DD + tile_n;

    float acc[4][4][4];
#pragma unroll
    for (int i = 0; i < 4; i++)
#pragma unroll
        for (int j = 0; j < 4; j++)
#pragma unroll
            for (int q = 0; q < 4; q++) acc[i][j][q] = 0.0f;

    gemm_core(A0, A1, FF, B0, B1, DD, 2 * FF / BKT, FF / BKT, smu, acc);

    int lane = threadIdx.x & 31, wid = threadIdx.x >> 5;
    int wm = wid & 1, wn = wid >> 1;
    int g = lane >> 2, tig = lane & 3;
    const float* bp0 = b2p + (size_t)e0 * DD + tile_n;
    const float* bp1 = b2p + (size_t)e1 * DD + tile_n;
    float* C = out + ((size_t)b * TT + tile_m) * DD + tile_n;
#pragma unroll
    for (int mi = 0; mi < 4; mi++) {
#pragma unroll
        for (int h2 = 0; h2 < 2; h2++) {
            int row = wm * 64 + mi * 16 + g + h2 * 8;
            float* Crow = C + (size_t)row * DD;
#pragma unroll
            for (int ni = 0; ni < 4; ni++) {
                int col = wn * 32 + ni * 8 + 2 * tig;
                float2 o;
                o.x = acc[mi][ni][h2 * 2 + 0] + w0 * bp0[col]     + w1 * bp1[col];
                o.y = acc[mi][ni][h2 * 2 + 1] + w0 * bp0[col + 1] + w1 * bp1[col + 1];
                *(float2*)(Crow + col) = o;
            }
        }
    }
}

// ---------------------------------------------------------------------------
extern "C" void kernel_launch(void* const* d_in, const int* in_sizes, int n_in,
                              void* d_out, int out_size) {
    const float* x  = (const float*)d_in[0];
    const float* Wr = (const float*)d_in[1];
    const float* W1 = (const float*)d_in[2];
    const float* b1 = (const float*)d_in[3];
    const float* W2 = (const float*)d_in[4];
    const float* b2 = (const float*)d_in[5];
    float* out = (float*)d_out;

    static int inited = 0;
    if (!inited) {
        cudaFuncSetAttribute(moe_gemm1, cudaFuncAttributeMaxDynamicSharedMemorySize, SMEM_BYTES);
        cudaFuncSetAttribute(moe_gemm2, cudaFuncAttributeMaxDynamicSharedMemorySize, SMEM_BYTES);
        inited = 1;
    }

    prep_kernel<<<(BB * TT * DD / 4) / 256, 256>>>(x);
    pool_kernel<<<dim3(BB, DD / 256), 256>>>(x);
    route_kernel<<<1, 256>>>(Wr);
    moe_gemm1<<<dim3(FF / BN, TT / BM, BB * 2), NTH, SMEM_BYTES>>>(W1, b1);
    moe_gemm2<<<dim3(DD / BN, TT / BM, BB), NTH, SMEM_BYTES>>>(W2, b2, out);
}